// round 2
// baseline (speedup 1.0000x reference)
#include <cuda_runtime.h>
#include <cstdint>

#define NB    128
#define NPRI  32768
#define TOPK  400
#define KEEPK 200
#define T     512
#define WORDS 13          // ceil(400/32)
#define CONF_T 0.5f
#define NMS_T  0.5f
#define BIGNEG -1000000000.0f

// Static device scratch (no cudaMalloc allowed).
__device__ unsigned long long g_keys[NB * NPRI];
__device__ unsigned long long g_s0[NB * NPRI];
__device__ unsigned long long g_s1[NB * NPRI];

__device__ __forceinline__ unsigned int order_f(float f) {
    unsigned int u = __float_as_uint(f);
    return (u & 0x80000000u) ? ~u : (u | 0x80000000u);
}
__device__ __forceinline__ float unorder_f(unsigned int u) {
    unsigned int v = (u & 0x80000000u) ? (u ^ 0x80000000u) : ~u;
    return __uint_as_float(v);
}

__global__ __launch_bounds__(T)
void box_select_kernel(const float* __restrict__ pred,
                       const float* __restrict__ priors,
                       float* __restrict__ out) {
    const int b    = blockIdx.x;
    const int tid  = threadIdx.x;
    const int lane = tid & 31;
    const int wid  = tid >> 5;
    const float* P = pred + (size_t)b * NPRI * 6;

    __shared__ unsigned int hist[256];
    __shared__ unsigned long long s_top[512];
    __shared__ float s_x1[TOPK], s_y1[TOPK], s_x2[TOPK], s_y2[TOPK];
    __shared__ float s_ar[TOPK], s_sc[TOPK];
    __shared__ int   s_lab[TOPK];
    __shared__ unsigned int s_sup[TOPK * WORDS];
    __shared__ unsigned int s_keep[WORDS];
    __shared__ int s_v, s_k, s_cnt, s_n, s_nkeep;
    __shared__ unsigned long long s_kth;

    for (int i = tid; i < 256; i += T) hist[i] = 0;
    __syncthreads();

    // ---------------- Phase 0: keys + MSB-byte histogram -----------------
    unsigned long long* keys = g_keys + (size_t)b * NPRI;
    for (int i = tid; i < NPRI; i += T) {          // NPRI % T == 0: warps full
        float2 c = *reinterpret_cast<const float2*>(P + 6 * i + 4);
        float s = fmaxf(c.x, c.y);
        float m = (s > CONF_T) ? s : BIGNEG;
        unsigned int u = order_f(m);
        unsigned long long key =
            ((unsigned long long)u << 32) | (unsigned int)(0xFFFFFFFFu - (unsigned)i);
        keys[i] = key;
        int bin = (int)(u >> 24);
        unsigned peers = __match_any_sync(0xffffffffu, bin);
        if (lane == __ffs(peers) - 1) atomicAdd(&hist[bin], __popc(peers));
    }
    __syncthreads();

    // ---------------- Phase 1: exact radix select of 400th-largest key ---
    unsigned long long* bufA = g_s0 + (size_t)b * NPRI;
    unsigned long long* bufB = g_s1 + (size_t)b * NPRI;
    unsigned long long* src  = keys;
    int srcN = NPRI;
    int kk   = TOPK;
    unsigned long long kth = 0;
    bool have = false;

    for (int byt = 7; byt >= 0; --byt) {
        if (byt < 7) {
            for (int i = tid; i < 256; i += T) hist[i] = 0;
            __syncthreads();
            for (int i = tid; i < srcN; i += T)
                atomicAdd(&hist[(int)((src[i] >> (byt * 8)) & 255)], 1u);
            __syncthreads();
        }
        if (tid == 0) {
            int acc = 0, v = 255;
            for (v = 255; v >= 0; --v) { acc += (int)hist[v]; if (acc >= kk) break; }
            s_v = v; s_k = kk - (acc - (int)hist[v]); s_cnt = (int)hist[v];
        }
        __syncthreads();
        const int v = s_v; kk = s_k; const int cnt = s_cnt;

        if (cnt == kk) {
            // kth-largest = min key within this digit bin
            if (tid == 0) s_kth = ~0ull;
            __syncthreads();
            unsigned long long local = ~0ull;
            for (int i = tid; i < srcN; i += T) {
                unsigned long long e = src[i];
                if ((int)((e >> (byt * 8)) & 255) == v) local = min(local, e);
            }
            if (local != ~0ull) atomicMin(&s_kth, local);
            __syncthreads();
            kth = s_kth;
            have = true;
            break;
        }
        // compact the candidate bin
        if (tid == 0) s_n = 0;
        __syncthreads();
        unsigned long long* dst = (src == bufA) ? bufB : bufA;
        for (int i = tid; i < srcN; i += T) {
            unsigned long long e = src[i];
            if ((int)((e >> (byt * 8)) & 255) == v) {
                int p = atomicAdd(&s_n, 1);
                dst[p] = e;
            }
        }
        __syncthreads();
        src = dst; srcN = cnt;
    }
    if (!have) kth = src[0];   // keys unique -> srcN==1 here

    // ---------------- Phase 2: gather exactly TOPK keys ------------------
    if (tid == 0) s_n = 0;
    __syncthreads();
    for (int i = tid; i < NPRI; i += T) {
        unsigned long long e = keys[i];
        if (e >= kth) {
            int p = atomicAdd(&s_n, 1);
            if (p < 512) s_top[p] = e;
        }
    }
    __syncthreads();
    {
        int n = s_n;
        for (int i = tid; i < 512; i += T)
            if (i >= n) s_top[i] = 0ull;        // pads sort to the end (desc)
    }
    __syncthreads();

    // ---------------- Phase 3: bitonic sort 512, DESCENDING --------------
    for (int ksz = 2; ksz <= 512; ksz <<= 1)
        for (int j = ksz >> 1; j > 0; j >>= 1) {
            int ixj = tid ^ j;
            if (ixj > tid) {
                unsigned long long a = s_top[tid], c = s_top[ixj];
                bool sw = ((tid & ksz) == 0) ? (a < c) : (a > c);
                if (sw) { s_top[tid] = c; s_top[ixj] = a; }
            }
            __syncthreads();
        }

    // ---------------- Phase 4: decode candidate boxes --------------------
    if (tid < TOPK) {
        unsigned long long key = s_top[tid];
        unsigned int u = (unsigned int)(key >> 32);
        float sc = unorder_f(u);
        int idx = (int)(0xFFFFFFFFu - (unsigned int)(key & 0xFFFFFFFFu));
        s_sc[tid] = sc;
        const float* pp = P + 6 * idx;
        float l0 = pp[0], l1 = pp[1], l2 = pp[2], l3 = pp[3];
        float c0 = pp[4], c1 = pp[5];
        float4 pr = *reinterpret_cast<const float4*>(priors + 4 * idx);
        float cx = __fadd_rn(pr.x, __fmul_rn(__fmul_rn(l0, 0.1f), pr.z));
        float cy = __fadd_rn(pr.y, __fmul_rn(__fmul_rn(l1, 0.1f), pr.w));
        float w  = __fmul_rn(pr.z, expf(__fmul_rn(l2, 0.2f)));
        float h  = __fmul_rn(pr.w, expf(__fmul_rn(l3, 0.2f)));
        float x1 = __fsub_rn(cx, __fmul_rn(w, 0.5f));
        float y1 = __fsub_rn(cy, __fmul_rn(h, 0.5f));
        float x2 = __fadd_rn(cx, __fmul_rn(w, 0.5f));
        float y2 = __fadd_rn(cy, __fmul_rn(h, 0.5f));
        s_x1[tid] = x1; s_y1[tid] = y1; s_x2[tid] = x2; s_y2[tid] = y2;
        s_ar[tid] = __fmul_rn(__fsub_rn(x2, x1), __fsub_rn(y2, y1));
        s_lab[tid] = (c1 > c0) ? 1 : 0;
    }
    __syncthreads();

    // ---------------- Phase 5: suppression bitmask via ballots ------------
    {
        const int NW = T / 32;
        for (int task = wid; task < TOPK * WORDS; task += NW) {
            int i = task / WORDS;
            int w = task - i * WORDS;
            int j = w * 32 + lane;
            bool sbit = false;
            if (j < TOPK && j > i) {
                float iw = fmaxf(__fsub_rn(fminf(s_x2[i], s_x2[j]),
                                           fmaxf(s_x1[i], s_x1[j])), 0.0f);
                float ih = fmaxf(__fsub_rn(fminf(s_y2[i], s_y2[j]),
                                           fmaxf(s_y1[i], s_y1[j])), 0.0f);
                float inter = __fmul_rn(iw, ih);
                float den = __fadd_rn(__fsub_rn(__fadd_rn(s_ar[i], s_ar[j]), inter),
                                      1e-12f);
                sbit = (__fdiv_rn(inter, den) > NMS_T);
            }
            unsigned wd = __ballot_sync(0xffffffffu, sbit);
            if (lane == 0) s_sup[task] = wd;
        }
    }
    // keep init = valid (score > CONF_T)
    if (tid < WORDS * 32) {          // warps 0..12, all full
        bool v = (tid < TOPK) && (s_sc[tid] > CONF_T);
        unsigned m = __ballot_sync(0xffffffffu, v);
        if (lane == 0) s_keep[wid] = m;
    }
    __syncthreads();

    // ---------------- Phase 6: greedy NMS (single thread, bit-skip) -------
    if (tid == 0) {
        unsigned kp[WORDS];
        #pragma unroll
        for (int w = 0; w < WORDS; w++) kp[w] = s_keep[w];
        int i = 0;
        while (i < TOPK) {
            int wi = i >> 5;
            unsigned m = kp[wi] & (0xFFFFFFFFu << (i & 31));
            if (!m) { i = (wi + 1) << 5; continue; }
            i = (wi << 5) + (__ffs(m) - 1);
            const unsigned* row = &s_sup[i * WORDS];
            #pragma unroll
            for (int w = 0; w < WORDS; w++) kp[w] &= ~row[w];
            i++;
        }
        int nk = 0;
        #pragma unroll
        for (int w = 0; w < WORDS; w++) { s_keep[w] = kp[w]; nk += __popc(kp[w]); }
        s_nkeep = nk;
    }
    __syncthreads();

    // ---------------- Phase 7: stable ascending sort of kept --------------
    {
        int i = tid;
        unsigned long long key2 = ~0ull;
        bool kept = (i < TOPK) && ((s_keep[i >> 5] >> (i & 31)) & 1u);
        if (kept) {
            unsigned u = order_f(s_sc[i]);
            key2 = ((unsigned long long)u << 32) | (unsigned)i;
        }
        s_top[i] = key2;
    }
    __syncthreads();
    for (int ksz = 2; ksz <= 512; ksz <<= 1)
        for (int j = ksz >> 1; j > 0; j >>= 1) {
            int ixj = tid ^ j;
            if (ixj > tid) {
                unsigned long long a = s_top[tid], c = s_top[ixj];
                bool sw = ((tid & ksz) == 0) ? (a > c) : (a < c);
                if (sw) { s_top[tid] = c; s_top[ixj] = a; }
            }
            __syncthreads();
        }

    // ---------------- Phase 8: emit output -------------------------------
    {
        float* ob = out + (size_t)b * (KEEPK * 6);
        int nk = min(s_nkeep, KEEPK);
        for (int r = tid; r < KEEPK; r += T) {
            float o0 = 0.f, o1 = 0.f, o2 = 0.f, o3 = 0.f, o4 = 0.f, o5 = 0.f;
            if (r < nk) {
                int pos = (int)(s_top[r] & 0xFFFFFFFFull);
                o0 = (float)s_lab[pos];
                o1 = s_sc[pos];
                o2 = s_x1[pos]; o3 = s_y1[pos];
                o4 = s_x2[pos]; o5 = s_y2[pos];
            }
            ob[r * 6 + 0] = o0; ob[r * 6 + 1] = o1; ob[r * 6 + 2] = o2;
            ob[r * 6 + 3] = o3; ob[r * 6 + 4] = o4; ob[r * 6 + 5] = o5;
        }
    }
}

extern "C" void kernel_launch(void* const* d_in, const int* in_sizes, int n_in,
                              void* d_out, int out_size) {
    const float* pred   = (const float*)d_in[0];
    const float* priors = (const float*)d_in[1];
    int b = in_sizes[0] / (NPRI * 6);
    if (b <= 0) b = NB;
    box_select_kernel<<<b, T>>>(pred, priors, (float*)d_out);
}